// round 7
// baseline (speedup 1.0000x reference)
#include <cuda_runtime.h>
#include <stdint.h>

// Problem constants (fixed by the dataset problem).
#define HH 112
#define WW 112
#define HW (HH * WW)
#define MAXB 4   // scratch sized for up to 4 batches

// Per-pixel key block: 4 u64 slots (3 channels + 1 pad => 32B aligned).
//   slot j (j=0,1,2): high 32 = order-preserving encoded flat depth,
//                     low  32 = float bits of triangle's flat color, channel j
// atomicMax (return discarded -> REDG) selects the max-depth triangle; the
// color payload rides along. 0 = "uncovered". Zero-initialized at module
// load; resolve re-zeros after consuming (invariant across graph replays).
__device__ unsigned long long g_keys[MAXB * HW * 4];

__device__ __forceinline__ unsigned int fenc(float f) {
    unsigned int u = __float_as_uint(f);
    return (u & 0x80000000u) ? ~u : (u | 0x80000000u);
}

// One thread per TRIANGLE; handles all batches (indices are batch-invariant).
__global__ void __launch_bounds__(256)
raster_kernel(const float* __restrict__ vertices,
              const float* __restrict__ colors,
              const int*   __restrict__ triangles,
              int B, int ntri, int nver) {
    int t = blockIdx.x * blockDim.x + threadIdx.x;
    if (t >= ntri) return;

    // First L2 trip: 3 independent index loads (shared across batches).
    int i0 = __ldg(&triangles[t]);
    int i1 = __ldg(&triangles[ntri + t]);
    int i2 = __ldg(&triangles[2 * ntri + t]);

    for (int b = 0; b < B; ++b) {
        // Second L2 trip: 18 independent gathers.
        const float* V = vertices + (size_t)b * 3 * nver;
        const float* C = colors   + (size_t)b * 3 * nver;
        float x0 = __ldg(&V[i0]),            x1 = __ldg(&V[i1]),            x2 = __ldg(&V[i2]);
        float y0 = __ldg(&V[nver + i0]),     y1 = __ldg(&V[nver + i1]),     y2 = __ldg(&V[nver + i2]);
        float z0 = __ldg(&V[2 * nver + i0]), z1 = __ldg(&V[2 * nver + i1]), z2 = __ldg(&V[2 * nver + i2]);
        float r0 = __ldg(&C[i0]),            r1 = __ldg(&C[i1]),            r2 = __ldg(&C[i2]);
        float g0 = __ldg(&C[nver + i0]),     g1 = __ldg(&C[nver + i1]),     g2 = __ldg(&C[nver + i2]);
        float b0 = __ldg(&C[2 * nver + i0]), b1 = __ldg(&C[2 * nver + i1]), b2 = __ldg(&C[2 * nver + i2]);

        float depth = ((z0 + z1) + z2) / 3.0f;
        float cr = ((r0 + r1) + r2) / 3.0f;
        float cg = ((g0 + g1) + g2) / 3.0f;
        float cb = ((b0 + b1) + b2) / 3.0f;

        float xmin = fminf(fminf(x0, x1), x2);
        float xmax = fmaxf(fmaxf(x0, x1), x2);
        float ymin = fminf(fminf(y0, y1), y2);
        float ymax = fmaxf(fmaxf(y0, y1), y2);

        // Match reference: max(ceil(min),0), min(floor(max), dim-1) in float, cast.
        int umin = (int)fmaxf(ceilf(xmin), 0.0f);
        int umax = (int)fminf(floorf(xmax), (float)(WW - 1));
        int vmin = (int)fmaxf(ceilf(ymin), 0.0f);
        int vmax = (int)fminf(floorf(ymax), (float)(HH - 1));
        if (umin > umax || vmin > vmax) continue;

        unsigned long long dhi = (unsigned long long)fenc(depth) << 32;
        unsigned long long kr = dhi | __float_as_uint(cr);
        unsigned long long kg = dhi | __float_as_uint(cg);
        unsigned long long kb = dhi | __float_as_uint(cb);

        size_t pb = (size_t)b * HW;
        for (int v = vmin; v <= vmax; ++v) {
            size_t rowoff = (pb + (size_t)v * WW) * 4;
            for (int u = umin; u <= umax; ++u) {
                unsigned long long* slot = &g_keys[rowoff + (size_t)u * 4];
                atomicMax(&slot[0], kr);   // return discarded -> REDG
                atomicMax(&slot[1], kg);
                atomicMax(&slot[2], kb);
            }
        }
    }
}

// One thread per pixel: 2x LDG.128 (3 keys + pad), branchless decode,
// 2x STG.128 reset, coalesced scalar output stores.
__global__ void __launch_bounds__(256)
resolve_kernel(float* __restrict__ out, int B) {
    int tid  = blockIdx.x * blockDim.x + threadIdx.x;
    int npix = B * HW;
    if (tid >= npix) return;
    int b   = tid / HW;
    int pix = tid - b * HW;

    uint4* slot = reinterpret_cast<uint4*>(&g_keys[(size_t)tid * 4]);
    uint4 a = __ldcg(slot);        // kr: (a.x lo, a.y hi), kg: (a.z lo, a.w hi)
    uint4 c = __ldcg(slot + 1);    // kb: (c.x lo, c.y hi), pad
    uint4 z = make_uint4(0u, 0u, 0u, 0u);
    slot[0] = z;                   // restore zero invariant for next replay
    slot[1] = z;

    bool cov = (a.y != 0u);        // encoded depth of kr; 0 = uncovered
    float mask = cov ? 1.0f : 0.0f;
    float c0 = cov ? __uint_as_float(a.x) : 0.0f;
    float c1 = cov ? __uint_as_float(a.z) : 0.0f;
    float c2 = cov ? __uint_as_float(c.x) : 0.0f;

    // Output layout: face_mask [B,1,H,W] then image [B,3,H,W], flattened.
    out[(size_t)b * HW + pix] = mask;
    float* img = out + (size_t)B * HW;
    img[((size_t)b * 3 + 0) * HW + pix] = c0;
    img[((size_t)b * 3 + 1) * HW + pix] = c1;
    img[((size_t)b * 3 + 2) * HW + pix] = c2;
}

extern "C" void kernel_launch(void* const* d_in, const int* in_sizes, int n_in,
                              void* d_out, int out_size) {
    const float* vertices  = (const float*)d_in[0];
    const float* colors    = (const float*)d_in[1];
    const int*   triangles = (const int*)d_in[2];

    int ntri = in_sizes[2] / 3;
    int B    = out_size / (4 * HW);
    int nver = in_sizes[0] / (3 * B);
    float* out = (float*)d_out;

    raster_kernel<<<(ntri + 255) / 256, 256>>>(vertices, colors, triangles,
                                               B, ntri, nver);

    int npix = B * HW;
    resolve_kernel<<<(npix + 255) / 256, 256>>>(out, B);
}

// round 8
// speedup vs baseline: 1.1895x; 1.1895x over previous
#include <cuda_runtime.h>
#include <stdint.h>

// Problem constants (fixed by the dataset problem).
#define HH 112
#define WW 112
#define HW (HH * WW)
#define MAXB 4   // scratch sized for up to 4 batches

// Per-pixel key block: 4 u64 slots (3 channels + pad => one 32B unit).
//   slot j (j=0,1,2): high 32 = order-preserving encoded flat depth,
//                     low  32 = float bits of triangle's flat color, channel j
// atomicMax (return discarded -> REDG) selects the max-depth triangle; the
// color payload rides along. 0 = "uncovered". Zero-initialized at module
// load; phase B re-zeros after consuming (invariant across graph replays).
__device__ unsigned long long g_keys[MAXB * HW * 4];

// Grid barrier state. g_gen is monotonic across replays (equality-compared,
// wrap-safe); g_count resets to 0 each replay by the last arriver.
__device__ unsigned int g_count = 0;
__device__ unsigned int g_gen   = 0;

__device__ __forceinline__ unsigned int fenc(float f) {
    unsigned int u = __float_as_uint(f);
    return (u & 0x80000000u) ? ~u : (u | 0x80000000u);
}

__global__ void __launch_bounds__(256, 1)
fused_raster(const float* __restrict__ vertices,
             const float* __restrict__ colors,
             const int*   __restrict__ triangles,
             float* __restrict__ out,
             int B, int ntri, int nver, int nblocks) {
    const int nwork = B * ntri;

    // ---------------- Phase A: scatter raster ----------------
    // Transposed mapping spreads tasks over ALL blocks (each block ~nwork/nblocks
    // tasks), minimizing the slowest-block arrival time at the barrier.
    int task = threadIdx.x * gridDim.x + blockIdx.x;
    if (task < nwork) {
        int b = task / ntri;
        int t = task - b * ntri;

        int i0 = __ldg(&triangles[t]);
        int i1 = __ldg(&triangles[ntri + t]);
        int i2 = __ldg(&triangles[2 * ntri + t]);

        const float* V = vertices + (size_t)b * 3 * nver;
        const float* C = colors   + (size_t)b * 3 * nver;
        float x0 = __ldg(&V[i0]),            x1 = __ldg(&V[i1]),            x2 = __ldg(&V[i2]);
        float y0 = __ldg(&V[nver + i0]),     y1 = __ldg(&V[nver + i1]),     y2 = __ldg(&V[nver + i2]);
        float z0 = __ldg(&V[2 * nver + i0]), z1 = __ldg(&V[2 * nver + i1]), z2 = __ldg(&V[2 * nver + i2]);
        float r0 = __ldg(&C[i0]),            r1 = __ldg(&C[i1]),            r2 = __ldg(&C[i2]);
        float g0 = __ldg(&C[nver + i0]),     g1 = __ldg(&C[nver + i1]),     g2 = __ldg(&C[nver + i2]);
        float b0 = __ldg(&C[2 * nver + i0]), b1 = __ldg(&C[2 * nver + i1]), b2 = __ldg(&C[2 * nver + i2]);

        float depth = ((z0 + z1) + z2) / 3.0f;
        float cr = ((r0 + r1) + r2) / 3.0f;
        float cg = ((g0 + g1) + g2) / 3.0f;
        float cb = ((b0 + b1) + b2) / 3.0f;

        float xmin = fminf(fminf(x0, x1), x2);
        float xmax = fmaxf(fmaxf(x0, x1), x2);
        float ymin = fminf(fminf(y0, y1), y2);
        float ymax = fmaxf(fmaxf(y0, y1), y2);

        // Match reference: max(ceil(min),0), min(floor(max), dim-1) in float, cast.
        int umin = (int)fmaxf(ceilf(xmin), 0.0f);
        int umax = (int)fminf(floorf(xmax), (float)(WW - 1));
        int vmin = (int)fmaxf(ceilf(ymin), 0.0f);
        int vmax = (int)fminf(floorf(ymax), (float)(HH - 1));

        if (umin <= umax && vmin <= vmax) {
            unsigned long long dhi = (unsigned long long)fenc(depth) << 32;
            unsigned long long kr = dhi | __float_as_uint(cr);
            unsigned long long kg = dhi | __float_as_uint(cg);
            unsigned long long kb = dhi | __float_as_uint(cb);

            size_t pb = (size_t)b * HW;
            for (int v = vmin; v <= vmax; ++v) {
                size_t rowoff = (pb + (size_t)v * WW) * 4;
                for (int u = umin; u <= umax; ++u) {
                    unsigned long long* slot = &g_keys[rowoff + (size_t)u * 4];
                    atomicMax(&slot[0], kr);   // return discarded -> REDG
                    atomicMax(&slot[1], kg);
                    atomicMax(&slot[2], kb);
                }
            }
        }
    }

    // -------- Grid barrier: cheap RED arrival + hot-spin load poll ----------
    __threadfence();      // order this thread's REDs device-wide
    __syncthreads();
    if (threadIdx.x == 0) {
        volatile unsigned int* vgen = &g_gen;
        unsigned int my_gen = *vgen;                    // read BEFORE arriving
        unsigned int ticket = atomicAdd(&g_count, 1u);  // contended RMW ~0.854 cyc/lane
        if (ticket == (unsigned int)nblocks - 1u) {
            g_count = 0u;                               // no racing writers remain
            __threadfence();
            atomicAdd(&g_gen, 1u);                      // release (monotonic)
        } else {
            while (*vgen == my_gen) { }                 // hot spin: L2 loads, broadcast
        }
        __threadfence();
    }
    __syncthreads();

    // ---------------- Phase B: resolve + reset (linear, coalesced) ----------
    const int tid  = blockIdx.x * blockDim.x + threadIdx.x;
    const int npix = B * HW;
    if (tid < npix) {
        int b   = tid / HW;
        int pix = tid - b * HW;

        uint4* slot = reinterpret_cast<uint4*>(&g_keys[(size_t)tid * 4]);
        uint4 a = __ldcg(slot);        // kr:(a.x lo, a.y hi)  kg:(a.z lo, a.w hi)
        uint4 c = __ldcg(slot + 1);    // kb:(c.x lo, c.y hi)  pad
        uint4 z = make_uint4(0u, 0u, 0u, 0u);
        slot[0] = z;                   // restore zero invariant for next replay
        slot[1] = z;

        bool cov = (a.y != 0u);        // encoded depth; 0 = uncovered
        float mask = cov ? 1.0f : 0.0f;
        float c0 = cov ? __uint_as_float(a.x) : 0.0f;
        float c1 = cov ? __uint_as_float(a.z) : 0.0f;
        float c2 = cov ? __uint_as_float(c.x) : 0.0f;

        // Output layout: face_mask [B,1,H,W] then image [B,3,H,W], flattened.
        out[(size_t)b * HW + pix] = mask;
        float* img = out + (size_t)B * HW;
        img[((size_t)b * 3 + 0) * HW + pix] = c0;
        img[((size_t)b * 3 + 1) * HW + pix] = c1;
        img[((size_t)b * 3 + 2) * HW + pix] = c2;
    }
}

extern "C" void kernel_launch(void* const* d_in, const int* in_sizes, int n_in,
                              void* d_out, int out_size) {
    const float* vertices  = (const float*)d_in[0];
    const float* colors    = (const float*)d_in[1];
    const int*   triangles = (const int*)d_in[2];

    int ntri = in_sizes[2] / 3;
    int B    = out_size / (4 * HW);
    int nver = in_sizes[0] / (3 * B);
    float* out = (float*)d_out;

    int npix    = B * HW;                           // 25088 for B=2
    int threads = 256;
    int nblocks = (npix + threads - 1) / threads;   // 98 blocks < 148 SMs: all resident

    fused_raster<<<nblocks, threads>>>(vertices, colors, triangles, out,
                                       B, ntri, nver, nblocks);
}

// round 9
// speedup vs baseline: 1.2710x; 1.0685x over previous
#include <cuda_runtime.h>
#include <stdint.h>

// Problem constants (fixed by the dataset problem).
#define HH 112
#define WW 112
#define HW (HH * WW)
#define MAXB 4   // scratch sized for up to 4 batches

// Per-pixel key block: 4 u64 slots (3 channels + pad => one 32B unit).
//   slot j (j=0,1,2): high 32 = order-preserving encoded flat depth,
//                     low  32 = float bits of triangle's flat color, channel j
// atomicMax (return discarded -> REDG) selects the max-depth triangle; the
// color payload rides along. Ties between bit-equal depths of distinct
// triangles resolve by color bits instead of lowest index (duplicate triangles
// carry identical colors, so benign). 0 = "uncovered". Zero-initialized at
// module load; resolve re-zeros after consuming (invariant across replays).
__device__ unsigned long long g_keys[MAXB * HW * 4];

__device__ __forceinline__ unsigned int fenc(float f) {
    unsigned int u = __float_as_uint(f);
    return (u & 0x80000000u) ? ~u : (u | 0x80000000u);
}

// One thread per (batch, triangle).
__global__ void __launch_bounds__(256)
raster_kernel(const float* __restrict__ vertices,
              const float* __restrict__ colors,
              const int*   __restrict__ triangles,
              int B, int ntri, int nver) {
    int idx = blockIdx.x * blockDim.x + threadIdx.x;
    if (idx >= B * ntri) return;
    int b = idx / ntri;
    int t = idx - b * ntri;

    // First L2 trip: 3 independent index loads.
    int i0 = __ldg(&triangles[t]);
    int i1 = __ldg(&triangles[ntri + t]);
    int i2 = __ldg(&triangles[2 * ntri + t]);

    // Second L2 trip: 18 independent gathers once indices land.
    const float* V = vertices + (size_t)b * 3 * nver;
    const float* C = colors   + (size_t)b * 3 * nver;
    float x0 = __ldg(&V[i0]),            x1 = __ldg(&V[i1]),            x2 = __ldg(&V[i2]);
    float y0 = __ldg(&V[nver + i0]),     y1 = __ldg(&V[nver + i1]),     y2 = __ldg(&V[nver + i2]);
    float z0 = __ldg(&V[2 * nver + i0]), z1 = __ldg(&V[2 * nver + i1]), z2 = __ldg(&V[2 * nver + i2]);
    float r0 = __ldg(&C[i0]),            r1 = __ldg(&C[i1]),            r2 = __ldg(&C[i2]);
    float g0 = __ldg(&C[nver + i0]),     g1 = __ldg(&C[nver + i1]),     g2 = __ldg(&C[nver + i2]);
    float b0 = __ldg(&C[2 * nver + i0]), b1 = __ldg(&C[2 * nver + i1]), b2 = __ldg(&C[2 * nver + i2]);

    float depth = ((z0 + z1) + z2) / 3.0f;
    float cr = ((r0 + r1) + r2) / 3.0f;
    float cg = ((g0 + g1) + g2) / 3.0f;
    float cb = ((b0 + b1) + b2) / 3.0f;

    float xmin = fminf(fminf(x0, x1), x2);
    float xmax = fmaxf(fmaxf(x0, x1), x2);
    float ymin = fminf(fminf(y0, y1), y2);
    float ymax = fmaxf(fmaxf(y0, y1), y2);

    // Match reference: max(ceil(min),0), min(floor(max), dim-1) in float, cast.
    int umin = (int)fmaxf(ceilf(xmin), 0.0f);
    int umax = (int)fminf(floorf(xmax), (float)(WW - 1));
    int vmin = (int)fmaxf(ceilf(ymin), 0.0f);
    int vmax = (int)fminf(floorf(ymax), (float)(HH - 1));
    if (umin > umax || vmin > vmax) return;

    unsigned long long dhi = (unsigned long long)fenc(depth) << 32;
    unsigned long long kr = dhi | __float_as_uint(cr);
    unsigned long long kg = dhi | __float_as_uint(cg);
    unsigned long long kb = dhi | __float_as_uint(cb);

    size_t pb = (size_t)b * HW;
    for (int v = vmin; v <= vmax; ++v) {
        size_t rowoff = (pb + (size_t)v * WW) * 4;
        for (int u = umin; u <= umax; ++u) {
            unsigned long long* slot = &g_keys[rowoff + (size_t)u * 4];
            atomicMax(&slot[0], kr);   // return discarded -> REDG
            atomicMax(&slot[1], kg);
            atomicMax(&slot[2], kb);
        }
    }
}

// One thread per pixel: 2x LDG.128 (3 keys + pad), branchless decode,
// 2x STG.128 reset, coalesced scalar output stores.
__global__ void __launch_bounds__(256)
resolve_kernel(float* __restrict__ out, int B) {
    int tid  = blockIdx.x * blockDim.x + threadIdx.x;
    int npix = B * HW;
    if (tid >= npix) return;
    int b   = tid / HW;
    int pix = tid - b * HW;

    uint4* slot = reinterpret_cast<uint4*>(&g_keys[(size_t)tid * 4]);
    uint4 a = __ldcg(slot);        // kr:(a.x lo, a.y hi)  kg:(a.z lo, a.w hi)
    uint4 c = __ldcg(slot + 1);    // kb:(c.x lo, c.y hi)  pad
    uint4 z = make_uint4(0u, 0u, 0u, 0u);
    slot[0] = z;                   // restore zero invariant for next replay
    slot[1] = z;

    bool cov = (a.y != 0u);        // encoded depth; 0 = uncovered
    float mask = cov ? 1.0f : 0.0f;
    float c0 = cov ? __uint_as_float(a.x) : 0.0f;
    float c1 = cov ? __uint_as_float(a.z) : 0.0f;
    float c2 = cov ? __uint_as_float(c.x) : 0.0f;

    // Output layout: face_mask [B,1,H,W] then image [B,3,H,W], flattened.
    out[(size_t)b * HW + pix] = mask;
    float* img = out + (size_t)B * HW;
    img[((size_t)b * 3 + 0) * HW + pix] = c0;
    img[((size_t)b * 3 + 1) * HW + pix] = c1;
    img[((size_t)b * 3 + 2) * HW + pix] = c2;
}

extern "C" void kernel_launch(void* const* d_in, const int* in_sizes, int n_in,
                              void* d_out, int out_size) {
    const float* vertices  = (const float*)d_in[0];
    const float* colors    = (const float*)d_in[1];
    const int*   triangles = (const int*)d_in[2];

    int ntri = in_sizes[2] / 3;
    int B    = out_size / (4 * HW);
    int nver = in_sizes[0] / (3 * B);
    float* out = (float*)d_out;

    int nwork = B * ntri;
    raster_kernel<<<(nwork + 255) / 256, 256>>>(vertices, colors, triangles,
                                                B, ntri, nver);

    int npix = B * HW;
    resolve_kernel<<<(npix + 255) / 256, 256>>>(out, B);
}

// round 10
// speedup vs baseline: 1.5055x; 1.1845x over previous
#include <cuda_runtime.h>
#include <stdint.h>

// Problem constants (fixed by the dataset problem).
#define HH 112
#define WW 112
#define HW (HH * WW)
#define MAXB 4   // scratch sized for up to 4 batches

// Planar per-pixel per-channel winner keys:
//   high 32 = order-preserving encoded flat depth
//   low  32 = raw float bits of that triangle's flat color for this channel
// atomicMax (return discarded -> REDG) selects max-depth triangle; payload
// rides along. 0 = "uncovered". Zero-initialized at module load; resolve
// re-zeros after consuming (invariant across graph replays) — no init kernel.
__device__ unsigned long long g_kr[MAXB * HW];
__device__ unsigned long long g_kg[MAXB * HW];
__device__ unsigned long long g_kb[MAXB * HW];

__device__ __forceinline__ unsigned int fenc(float f) {
    unsigned int u = __float_as_uint(f);
    return (u & 0x80000000u) ? ~u : (u | 0x80000000u);
}

// One thread per (batch, triangle); 128-thread blocks (max CTA spread).
__global__ void __launch_bounds__(128)
raster_kernel(const float* __restrict__ vertices,
              const float* __restrict__ colors,
              const int*   __restrict__ triangles,
              int B, int ntri, int nver) {
    int idx = blockIdx.x * blockDim.x + threadIdx.x;
    if (idx >= B * ntri) return;
    int b = idx / ntri;
    int t = idx - b * ntri;

    // First L2 trip: 3 independent index loads.
    int i0 = __ldg(&triangles[t]);
    int i1 = __ldg(&triangles[ntri + t]);
    int i2 = __ldg(&triangles[2 * ntri + t]);

    // Second L2 trip: 18 independent gathers once indices land.
    const float* V = vertices + (size_t)b * 3 * nver;
    const float* C = colors   + (size_t)b * 3 * nver;
    float x0 = __ldg(&V[i0]),            x1 = __ldg(&V[i1]),            x2 = __ldg(&V[i2]);
    float y0 = __ldg(&V[nver + i0]),     y1 = __ldg(&V[nver + i1]),     y2 = __ldg(&V[nver + i2]);
    float z0 = __ldg(&V[2 * nver + i0]), z1 = __ldg(&V[2 * nver + i1]), z2 = __ldg(&V[2 * nver + i2]);
    float r0 = __ldg(&C[i0]),            r1 = __ldg(&C[i1]),            r2 = __ldg(&C[i2]);
    float g0 = __ldg(&C[nver + i0]),     g1 = __ldg(&C[nver + i1]),     g2 = __ldg(&C[nver + i2]);
    float b0 = __ldg(&C[2 * nver + i0]), b1 = __ldg(&C[2 * nver + i1]), b2 = __ldg(&C[2 * nver + i2]);

    float depth = ((z0 + z1) + z2) / 3.0f;
    float cr = ((r0 + r1) + r2) / 3.0f;
    float cg = ((g0 + g1) + g2) / 3.0f;
    float cb = ((b0 + b1) + b2) / 3.0f;

    float xmin = fminf(fminf(x0, x1), x2);
    float xmax = fmaxf(fmaxf(x0, x1), x2);
    float ymin = fminf(fminf(y0, y1), y2);
    float ymax = fmaxf(fmaxf(y0, y1), y2);

    // Match reference: max(ceil(min),0), min(floor(max), dim-1) in float, cast.
    int umin = (int)fmaxf(ceilf(xmin), 0.0f);
    int umax = (int)fminf(floorf(xmax), (float)(WW - 1));
    int vmin = (int)fmaxf(ceilf(ymin), 0.0f);
    int vmax = (int)fminf(floorf(ymax), (float)(HH - 1));
    if (umin > umax || vmin > vmax) return;

    unsigned long long dhi = (unsigned long long)fenc(depth) << 32;
    unsigned long long kr = dhi | __float_as_uint(cr);
    unsigned long long kg = dhi | __float_as_uint(cg);
    unsigned long long kb = dhi | __float_as_uint(cb);

    size_t pb = (size_t)b * HW;
    for (int v = vmin; v <= vmax; ++v) {
        size_t rowoff = pb + (size_t)v * WW;
        for (int u = umin; u <= umax; ++u) {
            atomicMax(&g_kr[rowoff + u], kr);   // return discarded -> REDG
            atomicMax(&g_kg[rowoff + u], kg);
            atomicMax(&g_kb[rowoff + u], kb);
        }
    }
}

// Two pixels per thread on the planar arrays: 3x LDG.128 (one per channel),
// 3x STG.128 reset, branchless decode, float2 coalesced output stores.
// HW is even, so a pixel pair never straddles a batch or image plane.
__global__ void __launch_bounds__(256)
resolve_kernel(float* __restrict__ out, int B) {
    int g    = blockIdx.x * blockDim.x + threadIdx.x;   // pixel-pair id
    int ngrp = B * HW / 2;
    if (g >= ngrp) return;
    int p2  = g * 2;
    int b   = p2 / HW;
    int pix = p2 - b * HW;

    uint4* kr2 = reinterpret_cast<uint4*>(&g_kr[p2]);   // 2 keys, 16B aligned
    uint4* kg2 = reinterpret_cast<uint4*>(&g_kg[p2]);
    uint4* kb2 = reinterpret_cast<uint4*>(&g_kb[p2]);
    uint4 akr = __ldcg(kr2);     // pix0: (.x lo, .y hi)   pix1: (.z lo, .w hi)
    uint4 akg = __ldcg(kg2);
    uint4 akb = __ldcg(kb2);
    uint4 z = make_uint4(0u, 0u, 0u, 0u);
    *kr2 = z;                    // restore zero invariant for next replay
    *kg2 = z;
    *kb2 = z;

    bool cov0 = (akr.y != 0u);
    bool cov1 = (akr.w != 0u);
    float2 m  = make_float2(cov0 ? 1.0f : 0.0f, cov1 ? 1.0f : 0.0f);
    float2 c0 = make_float2(cov0 ? __uint_as_float(akr.x) : 0.0f,
                            cov1 ? __uint_as_float(akr.z) : 0.0f);
    float2 c1 = make_float2(cov0 ? __uint_as_float(akg.x) : 0.0f,
                            cov1 ? __uint_as_float(akg.z) : 0.0f);
    float2 c2 = make_float2(cov0 ? __uint_as_float(akb.x) : 0.0f,
                            cov1 ? __uint_as_float(akb.z) : 0.0f);

    // Output layout: face_mask [B,1,H,W] then image [B,3,H,W]; 8B-aligned pairs.
    *reinterpret_cast<float2*>(&out[(size_t)b * HW + pix]) = m;
    float* img = out + (size_t)B * HW;
    *reinterpret_cast<float2*>(&img[((size_t)b * 3 + 0) * HW + pix]) = c0;
    *reinterpret_cast<float2*>(&img[((size_t)b * 3 + 1) * HW + pix]) = c1;
    *reinterpret_cast<float2*>(&img[((size_t)b * 3 + 2) * HW + pix]) = c2;
}

extern "C" void kernel_launch(void* const* d_in, const int* in_sizes, int n_in,
                              void* d_out, int out_size) {
    const float* vertices  = (const float*)d_in[0];
    const float* colors    = (const float*)d_in[1];
    const int*   triangles = (const int*)d_in[2];

    int ntri = in_sizes[2] / 3;
    int B    = out_size / (4 * HW);
    int nver = in_sizes[0] / (3 * B);
    float* out = (float*)d_out;

    int nwork = B * ntri;
    raster_kernel<<<(nwork + 127) / 128, 128>>>(vertices, colors, triangles,
                                                B, ntri, nver);

    int ngrp = B * HW / 2;
    resolve_kernel<<<(ngrp + 255) / 256, 256>>>(out, B);
}